// round 5
// baseline (speedup 1.0000x reference)
#include <cuda_runtime.h>
#include <cuda_fp16.h>
#include <cstdint>

#define N_NODES  20000
#define KN       32
#define CIN      512
#define COUT     512
#define KTOT     1024

#define BM       32
#define NSTRIPES (N_NODES / BM)      // 625
#define NCTA     148

#define AH       1032                // A row stride (halves); 2064B, %128=16 -> ldmatrix conflict-free
#define ABUF_H   (BM * AH)           // 33024 halves per A buffer
#define BH2      24                  // B row stride (halves); 48B -> ldmatrix conflict-free
#define BSTG_H   (COUT * BH2)        // 12288 halves per B stage (k16)
#define NKT      64                  // K steps of 16 halves

__device__ __half g_Wh[(size_t)COUT * KTOT];
__device__ float  g_bias[COUT];

// ---------------------------------------------------------------------------
// Kernel 0: W -> fp16 concat layout, bias sum
// ---------------------------------------------------------------------------
__global__ void __launch_bounds__(256) convert_kernel(
    const float* __restrict__ Wl, const float* __restrict__ bl,
    const float* __restrict__ Wr, const float* __restrict__ br)
{
    const int n = blockIdx.x;
    const int t = threadIdx.x;
    const int k = t * 4;
    const float* src = (k < CIN) ? (Wl + (size_t)n * CIN + k)
                                 : (Wr + (size_t)n * CIN + (k - CIN));
    float4 v = *reinterpret_cast<const float4*>(src);
    __half2* dst = reinterpret_cast<__half2*>(&g_Wh[(size_t)n * KTOT + k]);
    dst[0] = __floats2half2_rn(v.x, v.y);
    dst[1] = __floats2half2_rn(v.z, v.w);
    if (n == 0)
        for (int c = t; c < COUT; c += 256) g_bias[c] = bl[c] + br[c];
}

// ---------------------------------------------------------------------------
// PTX helpers
// ---------------------------------------------------------------------------
__device__ __forceinline__ void cp_async16_s(uint32_t saddr, const void* g) {
    asm volatile("cp.async.cg.shared.global [%0], [%1], 16;" :: "r"(saddr), "l"(g));
}
__device__ __forceinline__ void cp_commit() {
    asm volatile("cp.async.commit_group;");
}
template <int NW>
__device__ __forceinline__ void cp_wait() {
    asm volatile("cp.async.wait_group %0;" :: "n"(NW));
}
__device__ __forceinline__ void ldsm_x4(uint32_t r[4], uint32_t saddr) {
    asm volatile("ldmatrix.sync.aligned.m8n8.x4.shared.b16 {%0,%1,%2,%3}, [%4];"
                 : "=r"(r[0]), "=r"(r[1]), "=r"(r[2]), "=r"(r[3]) : "r"(saddr));
}
__device__ __forceinline__ void mma_f16(float c[4], const uint32_t a[4],
                                        uint32_t b0, uint32_t b1) {
    asm volatile(
        "mma.sync.aligned.m16n8k16.row.col.f32.f16.f16.f32 "
        "{%0,%1,%2,%3}, {%4,%5,%6,%7}, {%8,%9}, {%0,%1,%2,%3};\n"
        : "+f"(c[0]), "+f"(c[1]), "+f"(c[2]), "+f"(c[3])
        : "r"(a[0]), "r"(a[1]), "r"(a[2]), "r"(a[3]), "r"(b0), "r"(b1));
}

__device__ __forceinline__ uint32_t h2u(__half2 h) {
    return *reinterpret_cast<uint32_t*>(&h);
}

// ---------------------------------------------------------------------------
// Aggregation fill: stripe rows [row0, row0+32) -> fp16 A-cache [32][AH]
// cols 0..511 = x, cols 512..1023 = mean(neigh). Dual-column for 2x MLP.
// ---------------------------------------------------------------------------
template <int NT>
__device__ __forceinline__ void fill_A(const float* __restrict__ x,
                                       const float* __restrict__ neigh,
                                       int row0, __half* Adst, int t)
{
    // phase 1a: x rows (4096 float4 tasks)
#pragma unroll
    for (int i = 0; i < 4096 / NT; i++) {
        const int idx = t + i * NT;
        const int r   = idx >> 7;
        const int c4  = idx & 127;
        float4 v = __ldg(reinterpret_cast<const float4*>(x)
                         + (size_t)(row0 + r) * (CIN / 4) + c4);
        *reinterpret_cast<uint2*>(Adst + r * AH + c4 * 4) =
            make_uint2(h2u(__floats2half2_rn(v.x, v.y)),
                       h2u(__floats2half2_rn(v.z, v.w)));
    }
    // phase 1b: mean(neigh) — each thread reduces TWO c4 columns concurrently
#pragma unroll
    for (int i = 0; i < 2048 / NT; i++) {
        const int idx = t + i * NT;
        const int r   = idx >> 6;
        const int c4  = idx & 63;           // pairs with c4+64
        const float4* base = reinterpret_cast<const float4*>(neigh)
                             + (size_t)(row0 + r) * KN * (CIN / 4);
        float ax = 0.f, ay = 0.f, az = 0.f, aw = 0.f;
        float bx = 0.f, by = 0.f, bz = 0.f, bw = 0.f;
#pragma unroll 8
        for (int k = 0; k < KN; k++) {
            float4 va = __ldg(base + (size_t)k * (CIN / 4) + c4);
            float4 vb = __ldg(base + (size_t)k * (CIN / 4) + c4 + 64);
            ax += va.x; ay += va.y; az += va.z; aw += va.w;
            bx += vb.x; by += vb.y; bz += vb.z; bw += vb.w;
        }
        const float inv = 1.0f / (float)KN;
        *reinterpret_cast<uint2*>(Adst + r * AH + CIN + c4 * 4) =
            make_uint2(h2u(__floats2half2_rn(ax * inv, ay * inv)),
                       h2u(__floats2half2_rn(az * inv, aw * inv)));
        *reinterpret_cast<uint2*>(Adst + r * AH + CIN + (c4 + 64) * 4) =
            make_uint2(h2u(__floats2half2_rn(bx * inv, by * inv)),
                       h2u(__floats2half2_rn(bz * inv, bw * inv)));
    }
}

// ---------------------------------------------------------------------------
// Persistent warp-specialized kernel
// ---------------------------------------------------------------------------
__global__ void __launch_bounds__(512, 1) fused_kernel(
    const float* __restrict__ x,
    const float* __restrict__ neigh,
    float* __restrict__ out)
{
    extern __shared__ __half sm[];
    __half* Abuf = sm;                      // [2][BM][AH]
    __half* Bbuf = sm + 2 * ABUF_H;         // [4][COUT][BH2]

    const int tid  = threadIdx.x;
    const int lane = tid & 31;
    const int w    = tid >> 5;              // consumer warp id when tid<256
    const int s0   = blockIdx.x;

    // prologue: everyone fills stripe s0 into buffer 0
    fill_A<512>(x, neigh, s0 * BM, Abuf, tid);

    // consumer-only persistent state
    float bias0[8], bias1[8];
    uint32_t Abase = 0, Bbase = 0, a_lane = 0, b_lane = 0;
    int g = lane >> 2, t4 = lane & 3;
    if (tid < 256) {
#pragma unroll
        for (int nt = 0; nt < 8; nt++) {
            const int col = w * 64 + nt * 8 + 2 * t4;
            bias0[nt] = g_bias[col];
            bias1[nt] = g_bias[col + 1];
        }
        Abase = (uint32_t)__cvta_generic_to_shared(Abuf);
        Bbase = (uint32_t)__cvta_generic_to_shared(Bbuf);
        a_lane = (uint32_t)(((lane & 15) * AH + (lane >> 4) * 8) * 2);
        b_lane = (uint32_t)(((w * 64 + ((lane >> 4) << 3) + (lane & 7)) * BH2
                             + ((lane >> 3) & 1) * 8) * 2);
    }
    __syncthreads();

    int buf = 0;
#pragma unroll 1
    for (int s = s0; s < NSTRIPES; s += NCTA) {
        if (tid < 256) {
            // ======== consumer: GEMM stripe s, cols w*64..w*64+63 ========
            const uint32_t Ab = Abase + (uint32_t)(buf * ABUF_H * 2);

            float acc[2][8][4];
#pragma unroll
            for (int mt = 0; mt < 2; mt++)
#pragma unroll
                for (int nt = 0; nt < 8; nt++)
#pragma unroll
                    for (int q = 0; q < 4; q++) acc[mt][nt][q] = 0.f;

            // per-warp-private B k16 stage loader (64 rows x 32B each)
            auto issueB = [&](int kt) {
                const uint32_t dpar = (uint32_t)((kt & 3) * BSTG_H * 2);
#pragma unroll
                for (int i = 0; i < 4; i++) {
                    const int idx = lane + i * 32;      // 0..127
                    const int r   = w * 64 + (idx >> 1);
                    const int seg = idx & 1;
                    cp_async16_s(Bbase + dpar + (uint32_t)((r * BH2 + seg * 8) * 2),
                                 g_Wh + (size_t)r * KTOT + kt * 16 + seg * 8);
                }
                cp_commit();
            };

            issueB(0); issueB(1); issueB(2);
#pragma unroll 1
            for (int kt = 0; kt < NKT; kt++) {
                cp_wait<2>();                       // group kt complete
                if (kt + 3 < NKT) issueB(kt + 3);
                else              cp_commit();      // empty group keeps invariant

                const uint32_t apar = Ab + a_lane + (uint32_t)(kt * 32);
                const uint32_t bpar = Bbase + (uint32_t)((kt & 3) * BSTG_H * 2) + b_lane;
                uint32_t a0[4], a1[4];
                ldsm_x4(a0, apar);
                ldsm_x4(a1, apar + 16 * AH * 2);
#pragma unroll
                for (int p = 0; p < 4; p++) {
                    uint32_t b[4];
                    ldsm_x4(b, bpar + p * (16 * BH2 * 2));
                    mma_f16(acc[0][2 * p],     a0, b[0], b[1]);
                    mma_f16(acc[1][2 * p],     a1, b[0], b[1]);
                    mma_f16(acc[0][2 * p + 1], a0, b[2], b[3]);
                    mma_f16(acc[1][2 * p + 1], a1, b[2], b[3]);
                }
            }

            // epilogue
            const int m0 = s * BM;
#pragma unroll
            for (int mt = 0; mt < 2; mt++)
#pragma unroll
                for (int nt = 0; nt < 8; nt++) {
                    const int col = w * 64 + nt * 8 + 2 * t4;
                    const int row = m0 + mt * 16 + g;
                    *reinterpret_cast<float2*>(&out[(size_t)row * COUT + col]) =
                        make_float2(acc[mt][nt][0] + bias0[nt], acc[mt][nt][1] + bias1[nt]);
                    *reinterpret_cast<float2*>(&out[(size_t)(row + 8) * COUT + col]) =
                        make_float2(acc[mt][nt][2] + bias0[nt], acc[mt][nt][3] + bias1[nt]);
                }
        } else {
            // ======== producer: aggregate stripe s+NCTA into other buffer ========
            const int sn = s + NCTA;
            if (sn < NSTRIPES)
                fill_A<256>(x, neigh, sn * BM, Abuf + (buf ^ 1) * ABUF_H, tid - 256);
        }
        __syncthreads();
        buf ^= 1;
    }
}

// ---------------------------------------------------------------------------
extern "C" void kernel_launch(void* const* d_in, const int* in_sizes, int n_in,
                              void* d_out, int out_size) {
    const float* x  = (const float*)d_in[0];
    const float* nx = (const float*)d_in[1];
    const float* Wl = (const float*)d_in[2];
    const float* bl = (const float*)d_in[3];
    const float* Wr = (const float*)d_in[4];
    const float* br = (const float*)d_in[5];
    float* out = (float*)d_out;

    convert_kernel<<<COUT, 256>>>(Wl, bl, Wr, br);

    const int smem_bytes = (2 * ABUF_H + 4 * BSTG_H) * (int)sizeof(__half); // 230400
    cudaFuncSetAttribute(fused_kernel,
                         cudaFuncAttributeMaxDynamicSharedMemorySize, smem_bytes);
    fused_kernel<<<NCTA, 512, smem_bytes>>>(x, nx, out);
}

// round 6
// speedup vs baseline: 1.1137x; 1.1137x over previous
#include <cuda_runtime.h>
#include <cuda_fp16.h>
#include <cstdint>

#define N_NODES  20000
#define KN       32
#define CIN      512
#define COUT     512
#define KTOT     1024

#define BM       32
#define NSTRIPES (N_NODES / BM)      // 625
#define NCTA     148

#define AH       1032                // A row stride (halves); 2064B -> ldmatrix conflict-free
#define ABUF_H   (BM * AH)           // 33024 halves per A buffer
#define BH       40                  // B row stride (halves); 80B -> conflict-free
#define BSTG_H   (COUT * BH)         // 20480 halves per B stage (k32)
#define NKT      32                  // K steps of 32 halves

__device__ __half g_Wh[(size_t)COUT * KTOT];
__device__ float  g_bias[COUT];

// ---------------------------------------------------------------------------
// Kernel 0: W -> fp16 concat layout, bias sum
// ---------------------------------------------------------------------------
__global__ void __launch_bounds__(256) convert_kernel(
    const float* __restrict__ Wl, const float* __restrict__ bl,
    const float* __restrict__ Wr, const float* __restrict__ br)
{
    const int n = blockIdx.x;
    const int t = threadIdx.x;
    const int k = t * 4;
    const float* src = (k < CIN) ? (Wl + (size_t)n * CIN + k)
                                 : (Wr + (size_t)n * CIN + (k - CIN));
    float4 v = *reinterpret_cast<const float4*>(src);
    __half2* dst = reinterpret_cast<__half2*>(&g_Wh[(size_t)n * KTOT + k]);
    dst[0] = __floats2half2_rn(v.x, v.y);
    dst[1] = __floats2half2_rn(v.z, v.w);
    if (n == 0)
        for (int c = t; c < COUT; c += 256) g_bias[c] = bl[c] + br[c];
}

// ---------------------------------------------------------------------------
// PTX helpers
// ---------------------------------------------------------------------------
__device__ __forceinline__ void cp_async16_s(uint32_t saddr, const void* g) {
    asm volatile("cp.async.cg.shared.global [%0], [%1], 16;" :: "r"(saddr), "l"(g));
}
__device__ __forceinline__ void cp_commit() {
    asm volatile("cp.async.commit_group;");
}
template <int NW>
__device__ __forceinline__ void cp_wait() {
    asm volatile("cp.async.wait_group %0;" :: "n"(NW));
}
__device__ __forceinline__ void ldsm_x4(uint32_t r[4], uint32_t saddr) {
    asm volatile("ldmatrix.sync.aligned.m8n8.x4.shared.b16 {%0,%1,%2,%3}, [%4];"
                 : "=r"(r[0]), "=r"(r[1]), "=r"(r[2]), "=r"(r[3]) : "r"(saddr));
}
__device__ __forceinline__ void mma_f16(float c[4], const uint32_t a[4],
                                        uint32_t b0, uint32_t b1) {
    asm volatile(
        "mma.sync.aligned.m16n8k16.row.col.f32.f16.f16.f32 "
        "{%0,%1,%2,%3}, {%4,%5,%6,%7}, {%8,%9}, {%0,%1,%2,%3};\n"
        : "+f"(c[0]), "+f"(c[1]), "+f"(c[2]), "+f"(c[3])
        : "r"(a[0]), "r"(a[1]), "r"(a[2]), "r"(a[3]), "r"(b0), "r"(b1));
}
__device__ __forceinline__ uint32_t h2u(__half2 h) {
    return *reinterpret_cast<uint32_t*>(&h);
}

// ---------------------------------------------------------------------------
// Aggregation fill: stripe rows [row0,row0+32) -> fp16 A-cache [32][AH]
// cols 0..511 = x, cols 512..1023 = mean(neigh)
// ---------------------------------------------------------------------------
template <int NT>
__device__ __forceinline__ void fill_A(const float* __restrict__ x,
                                       const float* __restrict__ neigh,
                                       int row0, __half* Adst, int t)
{
#pragma unroll
    for (int i = 0; i < 4096 / NT; i++) {
        const int idx = t + i * NT;
        const int r   = idx >> 7;
        const int c4  = idx & 127;
        float4 v = __ldg(reinterpret_cast<const float4*>(x)
                         + (size_t)(row0 + r) * (CIN / 4) + c4);
        *reinterpret_cast<uint2*>(Adst + r * AH + c4 * 4) =
            make_uint2(h2u(__floats2half2_rn(v.x, v.y)),
                       h2u(__floats2half2_rn(v.z, v.w)));
    }
#pragma unroll
    for (int i = 0; i < 4096 / NT; i++) {
        const int idx = t + i * NT;
        const int r   = idx >> 7;
        const int c4  = idx & 127;
        const float4* base = reinterpret_cast<const float4*>(neigh)
                             + (size_t)(row0 + r) * KN * (CIN / 4) + c4;
        float sx = 0.f, sy = 0.f, sz = 0.f, sw = 0.f;
#pragma unroll 8
        for (int k = 0; k < KN; k++) {
            float4 v = __ldg(base + (size_t)k * (CIN / 4));
            sx += v.x; sy += v.y; sz += v.z; sw += v.w;
        }
        const float inv = 1.0f / (float)KN;
        *reinterpret_cast<uint2*>(Adst + r * AH + CIN + c4 * 4) =
            make_uint2(h2u(__floats2half2_rn(sx * inv, sy * inv)),
                       h2u(__floats2half2_rn(sz * inv, sw * inv)));
    }
}

// ---------------------------------------------------------------------------
// Persistent warp-specialized kernel: 16 consumer warps + 16 producer warps
// ---------------------------------------------------------------------------
__global__ void __launch_bounds__(1024, 1) fused_kernel(
    const float* __restrict__ x,
    const float* __restrict__ neigh,
    float* __restrict__ out)
{
    extern __shared__ __half sm[];
    __half* Abuf = sm;                      // [2][BM][AH]
    __half* Bbuf = sm + 2 * ABUF_H;         // [2][COUT][BH]

    const int tid  = threadIdx.x;
    const int lane = tid & 31;
    const int w    = tid >> 5;              // consumer warp id when tid<512
    const int s0   = blockIdx.x;

    // prologue: all 1024 threads fill stripe s0 into buffer 0
    fill_A<1024>(x, neigh, s0 * BM, Abuf, tid);

    uint32_t Abase = 0, Bbase = 0, a_lane = 0, b_lane = 0;
    const int g = lane >> 2, t4 = lane & 3;
    if (tid < 512) {
        Abase = (uint32_t)__cvta_generic_to_shared(Abuf);
        Bbase = (uint32_t)__cvta_generic_to_shared(Bbuf);
        a_lane = (uint32_t)(((lane & 15) * AH + (lane >> 4) * 8) * 2);
        b_lane = (uint32_t)(((w * 32 + ((lane >> 4) << 3) + (lane & 7)) * BH
                             + ((lane >> 3) & 1) * 8) * 2);
    }
    __syncthreads();

    int buf = 0;
#pragma unroll 1
    for (int s = s0; s < NSTRIPES; s += NCTA) {
        if (tid < 512) {
            // ===== consumer: GEMM stripe s, cols w*32 .. w*32+31 =====
            const uint32_t Ab = Abase + (uint32_t)(buf * ABUF_H * 2);

            float acc[2][4][4];
#pragma unroll
            for (int mt = 0; mt < 2; mt++)
#pragma unroll
                for (int nt = 0; nt < 4; nt++)
#pragma unroll
                    for (int q = 0; q < 4; q++) acc[mt][nt][q] = 0.f;

            // per-warp-private B stage: 32 rows x 64B (k32)
            auto issueB = [&](int kt) {
                const uint32_t dpar = (uint32_t)((kt & 1) * BSTG_H * 2);
#pragma unroll
                for (int i = 0; i < 4; i++) {
                    const int idx = lane + i * 32;      // 0..127
                    const int r   = w * 32 + (idx >> 2);
                    const int seg = idx & 3;
                    cp_async16_s(Bbase + dpar + (uint32_t)((r * BH + seg * 8) * 2),
                                 g_Wh + (size_t)r * KTOT + kt * 32 + seg * 8);
                }
                cp_commit();
            };

            issueB(0);
#pragma unroll 1
            for (int kt = 0; kt < NKT; kt++) {
                if (kt + 1 < NKT) { issueB(kt + 1); cp_wait<1>(); }
                else              { cp_wait<0>(); }

                const uint32_t apar = Ab + a_lane + (uint32_t)(kt * 64);
                const uint32_t bpar = Bbase + (uint32_t)((kt & 1) * BSTG_H * 2) + b_lane;
#pragma unroll
                for (int ks = 0; ks < 2; ks++) {
                    uint32_t a0[4], a1[4];
                    ldsm_x4(a0, apar + ks * 32);
                    ldsm_x4(a1, apar + ks * 32 + 16 * AH * 2);
#pragma unroll
                    for (int p = 0; p < 2; p++) {
                        uint32_t b[4];
                        ldsm_x4(b, bpar + ks * 32 + p * (16 * BH * 2));
                        mma_f16(acc[0][2 * p],     a0, b[0], b[1]);
                        mma_f16(acc[1][2 * p],     a1, b[0], b[1]);
                        mma_f16(acc[0][2 * p + 1], a0, b[2], b[3]);
                        mma_f16(acc[1][2 * p + 1], a1, b[2], b[3]);
                    }
                }
            }

            // epilogue (bias from gmem; L2-hot)
            const int m0 = s * BM;
#pragma unroll
            for (int mt = 0; mt < 2; mt++)
#pragma unroll
                for (int nt = 0; nt < 4; nt++) {
                    const int col = w * 32 + nt * 8 + 2 * t4;
                    const int row = m0 + mt * 16 + g;
                    const float b0v = __ldg(&g_bias[col]);
                    const float b1v = __ldg(&g_bias[col + 1]);
                    *reinterpret_cast<float2*>(&out[(size_t)row * COUT + col]) =
                        make_float2(acc[mt][nt][0] + b0v, acc[mt][nt][1] + b1v);
                    *reinterpret_cast<float2*>(&out[(size_t)(row + 8) * COUT + col]) =
                        make_float2(acc[mt][nt][2] + b0v, acc[mt][nt][3] + b1v);
                }
        } else {
            // ===== producer: aggregate stripe s+NCTA into other buffer =====
            const int sn = s + NCTA;
            if (sn < NSTRIPES)
                fill_A<512>(x, neigh, sn * BM, Abuf + (buf ^ 1) * ABUF_H, tid - 512);
        }
        __syncthreads();
        buf ^= 1;
    }
}

// ---------------------------------------------------------------------------
extern "C" void kernel_launch(void* const* d_in, const int* in_sizes, int n_in,
                              void* d_out, int out_size) {
    const float* x  = (const float*)d_in[0];
    const float* nx = (const float*)d_in[1];
    const float* Wl = (const float*)d_in[2];
    const float* bl = (const float*)d_in[3];
    const float* Wr = (const float*)d_in[4];
    const float* br = (const float*)d_in[5];
    float* out = (float*)d_out;

    convert_kernel<<<COUT, 256>>>(Wl, bl, Wr, br);

    const int smem_bytes = (2 * ABUF_H + 2 * BSTG_H) * (int)sizeof(__half); // 214016
    cudaFuncSetAttribute(fused_kernel,
                         cudaFuncAttributeMaxDynamicSharedMemorySize, smem_bytes);
    fused_kernel<<<NCTA, 1024, smem_bytes>>>(x, nx, out);
}